// round 5
// baseline (speedup 1.0000x reference)
#include <cuda_runtime.h>
#include <cuda_fp16.h>
#include <math.h>
#include <cstdint>

#define BATCH 128
#define NPT   500
#define NROWS (BATCH*NPT)

typedef unsigned long long ull;

// ---------------- scratch (static; no allocation) ----------------
__device__ __align__(256) __half g_hiP[65536000];
__device__ __align__(256) __half g_loP[65536000];
__device__ __align__(256) __half g_hiQ[65536000];
__device__ __align__(256) __half g_loQ[65536000];
__device__ __align__(256) float g_f32[65536000];
__device__ __align__(256) __half g_wH[742528];
__device__ __align__(256) int g_idx1[BATCH * 500];
__device__ __align__(256) int g_idx2[BATCH * 1000];

// weight arena offsets (elements, K padded to mult of 8)
#define OFF_W2   0
#define OFF_PC1  16384
#define OFF_W3   81920
#define OFF_W4   149504
#define OFF_PC2  247808
#define OFF_W5   395264
#define OFF_W6   545792

// ---------------- helpers ----------------
__device__ __forceinline__ uint32_t smem_u32(const void* p) {
    uint32_t a;
    asm("{ .reg .u64 t; cvta.to.shared.u64 t, %1; cvt.u32.u64 %0, t; }" : "=r"(a) : "l"(p));
    return a;
}
__device__ __forceinline__ void cpa16(uint32_t dst, const void* src, int sz) {
    asm volatile("cp.async.cg.shared.global [%0], [%1], 16, %2;"
        :: "r"(dst), "l"(src), "r"(sz) : "memory");
}
__device__ __forceinline__ void ldm_x4(uint32_t* r, uint32_t addr) {
    asm volatile("ldmatrix.sync.aligned.m8n8.x4.shared.b16 {%0,%1,%2,%3}, [%4];"
        : "=r"(r[0]), "=r"(r[1]), "=r"(r[2]), "=r"(r[3]) : "r"(addr));
}
__device__ __forceinline__ void ldm_x2(uint32_t& r0, uint32_t& r1, uint32_t addr) {
    asm volatile("ldmatrix.sync.aligned.m8n8.x2.shared.b16 {%0,%1}, [%2];"
        : "=r"(r0), "=r"(r1) : "r"(addr));
}
__device__ __forceinline__ void mma_f16(float* d, const uint32_t* a, uint32_t b0, uint32_t b1) {
    asm volatile("mma.sync.aligned.m16n8k16.row.col.f32.f16.f16.f32 "
        "{%0,%1,%2,%3}, {%4,%5,%6,%7}, {%8,%9}, {%0,%1,%2,%3};"
        : "+f"(d[0]), "+f"(d[1]), "+f"(d[2]), "+f"(d[3])
        : "r"(a[0]), "r"(a[1]), "r"(a[2]), "r"(a[3]), "r"(b0), "r"(b1));
}
// split a pair of fp32 -> packed fp16 hi word + fp16 residual word
__device__ __forceinline__ void split2h(float v0, float v1, uint32_t& h, uint32_t& l) {
    __half2 hh = __floats2half2_rn(v0, v1);
    float2 bk = __half22float2(hh);
    __half2 ll = __floats2half2_rn(v0 - bk.x, v1 - bk.y);
    h = *(uint32_t*)&hh;
    l = *(uint32_t*)&ll;
}

// ---------------- fp16 2-term split HMMA GEMM ----------------
// C = relu?( sum_k A[m,k]*W[n,k] + bias[n] ),  A as fp16 (hi,lo), W single fp16.
// D = Ah*Wh + Al*Wh (fp32 accum).  CTA 128x256, 8 warps (2M x 4N), warp 64x64.
// 3-stage cp.async pipeline; stage = Ah 16K | Al 16K | Wh 32K = 64KB.
#define NSTG 3
#define STG 65536
static const int GEMM_SMEM = NSTG * STG;

__device__ __forceinline__ void g_fill(
    const __half* __restrict__ Ah, const __half* __restrict__ Al,
    const __half* __restrict__ Wh,
    int N, int K, int row0, int col0, int s, int nst, uint32_t sb, int tid)
{
    if (s < nst) {
        int k0 = s << 6;
        uint32_t base = sb + (uint32_t)(s % NSTG) * STG;
        // A: 128 rows x 8 chunks, hi+lo
#pragma unroll
        for (int i = 0; i < 4; i++) {
            int g = (i << 8) + tid;
            int r = g >> 3, c = g & 7;
            int kg = k0 + (c << 3);
            int ok = (kg < K) ? 16 : 0;
            uint32_t d = base + ((uint32_t)r << 7) + (((uint32_t)(c ^ (r & 7))) << 4);
            size_t ao = (size_t)(row0 + r) * K + kg;
            cpa16(d,         Ah + ao, ok);
            cpa16(d + 16384, Al + ao, ok);
        }
        // W: 256 rows x 8 chunks, hi only
#pragma unroll
        for (int i = 0; i < 8; i++) {
            int g = (i << 8) + tid;
            int r = g >> 3, c = g & 7;
            int kg = k0 + (c << 3);
            int ok = (kg < K && (col0 + r) < N) ? 16 : 0;
            uint32_t d = base + 32768 + ((uint32_t)r << 7) + (((uint32_t)(c ^ (r & 7))) << 4);
            cpa16(d, Wh + (size_t)(col0 + r) * K + kg, ok);
        }
    }
    asm volatile("cp.async.commit_group;" ::: "memory");
}

__global__ void __launch_bounds__(256, 1)
gemm_f16(const __half* __restrict__ Ah, const __half* __restrict__ Al,
         const __half* __restrict__ Wh,
         const float* __restrict__ bias,
         float* __restrict__ Cf,
         __half* __restrict__ Chi, __half* __restrict__ Clo,
         int M, int N, int K, int relu, int mode)
{
    extern __shared__ char smem[];
    uint32_t sb = smem_u32(smem);
    int tid = threadIdx.x, lane = tid & 31, wid = tid >> 5;
    int warp_m = wid & 1;        // 64 rows
    int warp_n = wid >> 1;       // 64 cols
    int row0 = blockIdx.y << 7;
    int col0 = blockIdx.x << 8;
    int Nt = N - col0; if (Nt > 256) Nt = 256;
    int n_lim = Nt - warp_n * 64;
    int ni_cnt = (n_lim >= 64) ? 8 : (n_lim > 0 ? (n_lim >> 3) : 0);
    int nst = (K + 63) >> 6;

    float acc[4][8][4];
#pragma unroll
    for (int a = 0; a < 4; a++)
#pragma unroll
        for (int b = 0; b < 8; b++)
#pragma unroll
            for (int c = 0; c < 4; c++) acc[a][b][c] = 0.f;

    g_fill(Ah, Al, Wh, N, K, row0, col0, 0, nst, sb, tid);
    g_fill(Ah, Al, Wh, N, K, row0, col0, 1, nst, sb, tid);

    int a_row = warp_m * 64 + (lane & 15);
    int a_sel = lane >> 4;
    int b_row = warp_n * 64 + (lane & 7);
    int b_sel = (lane >> 3) & 1;

    for (int s = 0; s < nst; s++) {
        asm volatile("cp.async.wait_group 1;" ::: "memory");
        __syncthreads();
        uint32_t base = sb + (uint32_t)(s % NSTG) * STG;
        int kr = K - (s << 6);
        int kcnt = (kr + 15) >> 4; if (kcnt > 4) kcnt = 4;
        if (ni_cnt > 0) {
            for (int ks = 0; ks < kcnt; ks++) {
                uint32_t Fh[4][4], Fl[4][4];
                int ch_a = (ks << 1) + a_sel;
#pragma unroll
                for (int mi = 0; mi < 4; mi++) {
                    int rr = a_row + mi * 16;
                    uint32_t sw = base + ((uint32_t)rr << 7) + (((uint32_t)(ch_a ^ (rr & 7))) << 4);
                    ldm_x4(Fh[mi], sw);
                    ldm_x4(Fl[mi], sw + 16384);
                }
                int ch_b = (ks << 1) + b_sel;
                if (ni_cnt == 8) {
#pragma unroll
                    for (int ni = 0; ni < 8; ni++) {
                        int nr = b_row + ni * 8;
                        uint32_t sw = base + 32768 + ((uint32_t)nr << 7)
                                    + (((uint32_t)(ch_b ^ (nr & 7))) << 4);
                        uint32_t b0, b1;
                        ldm_x2(b0, b1, sw);
#pragma unroll
                        for (int mi = 0; mi < 4; mi++) {
                            mma_f16(acc[mi][ni], Fh[mi], b0, b1);
                            mma_f16(acc[mi][ni], Fl[mi], b0, b1);
                        }
                    }
                } else {
                    for (int ni = 0; ni < ni_cnt; ni++) {
                        int nr = b_row + ni * 8;
                        uint32_t sw = base + 32768 + ((uint32_t)nr << 7)
                                    + (((uint32_t)(ch_b ^ (nr & 7))) << 4);
                        uint32_t b0, b1;
                        ldm_x2(b0, b1, sw);
#pragma unroll
                        for (int mi = 0; mi < 4; mi++) {
                            mma_f16(acc[mi][ni], Fh[mi], b0, b1);
                            mma_f16(acc[mi][ni], Fl[mi], b0, b1);
                        }
                    }
                }
            }
        }
        g_fill(Ah, Al, Wh, N, K, row0, col0, s + 2, nst, sb, tid);
    }

    // epilogue
    int er = row0 + warp_m * 64 + (lane >> 2);
    int ec = col0 + warp_n * 64 + ((lane & 3) << 1);
    for (int ni = 0; ni < ni_cnt; ni++) {
        int c = ec + ni * 8;
        float b0 = __ldg(bias + c), b1 = __ldg(bias + c + 1);
#pragma unroll
        for (int mi = 0; mi < 4; mi++) {
            int r = er + mi * 16;
            float v00 = acc[mi][ni][0] + b0, v01 = acc[mi][ni][1] + b1;
            float v10 = acc[mi][ni][2] + b0, v11 = acc[mi][ni][3] + b1;
            if (relu) {
                v00 = fmaxf(v00, 0.f); v01 = fmaxf(v01, 0.f);
                v10 = fmaxf(v10, 0.f); v11 = fmaxf(v11, 0.f);
            }
            if (mode == 0) {
                *(float2*)(Cf + (size_t)r * N + c)       = make_float2(v00, v01);
                *(float2*)(Cf + (size_t)(r + 8) * N + c) = make_float2(v10, v11);
            } else {
                uint32_t h, l;
                split2h(v00, v01, h, l);
                *(uint32_t*)(Chi + (size_t)r * N + c) = h;
                *(uint32_t*)(Clo + (size_t)r * N + c) = l;
                split2h(v10, v11, h, l);
                *(uint32_t*)(Chi + (size_t)(r + 8) * N + c) = h;
                *(uint32_t*)(Clo + (size_t)(r + 8) * N + c) = l;
            }
        }
    }
}

// ---------------- weight pack (fp32 -> fp16, pad K) ----------------
__global__ void pack_w(const float* __restrict__ w2, const float* __restrict__ pc1,
                       const float* __restrict__ w3, const float* __restrict__ w4,
                       const float* __restrict__ pc2, const float* __restrict__ w5,
                       const float* __restrict__ w6) {
    int t = blockIdx.x * 256 + threadIdx.x;
    if (t >= 742400) return;
    float v;
    if (t < 81920) {
        v = (t < 16384) ? w2[t] : pc1[t - 16384];
    } else if (t < 149504) {
        int i = t - 81920; int r = i / 264, c = i - r * 264;
        v = (c < 259) ? w3[r * 259 + c] : 0.f;
    } else if (t < 247808) {
        v = w4[t - 149504];
    } else if (t < 395264) {
        v = pc2[t - 247808];
    } else if (t < 545792) {
        int i = t - 395264; int r = i / 392, c = i - r * 392;
        v = (c < 387) ? w5[r * 387 + c] : 0.f;
    } else {
        v = w6[t - 545792];
    }
    g_wH[t] = __float2half_rn(v);
}

// ---------------- fused conf + concat + first linear -> fp16 hi/lo ----------------
__global__ void point_mlp1(const float* __restrict__ x,
                           const float* __restrict__ confW, const float* __restrict__ confb,
                           const float* __restrict__ w1, const float* __restrict__ b1) {
    int t = blockIdx.x * 256 + threadIdx.x;
    if (t >= NROWS * 16) return;
    int p = t >> 4, g = t & 15;
    float x0 = x[p * 3], x1 = x[p * 3 + 1], x2 = x[p * 3 + 2];
    float s = confW[0] * x0 + confW[1] * x1 + confW[2] * x2 + confb[0];
    float conf = 1.f / (1.f + expf(-s));
    const float* wr = w1 + (g * 4) * 4;
    float v[4];
#pragma unroll
    for (int r = 0; r < 4; r++) {
        float a = b1[g * 4 + r]
                + wr[r * 4 + 0] * conf + wr[r * 4 + 1] * x0
                + wr[r * 4 + 2] * x1   + wr[r * 4 + 3] * x2;
        v[r] = fmaxf(a, 0.f);
    }
    uint32_t h0, l0, h1, l1;
    split2h(v[0], v[1], h0, l0);
    split2h(v[2], v[3], h1, l1);
    size_t o = (size_t)p * 64 + g * 4;
    *(uint2*)(g_hiP + o) = make_uint2(h0, h1);
    *(uint2*)(g_loP + o) = make_uint2(l0, l1);
}

// ---------------- farthest point sampling (bitwise-matches XLA) ----------------
__global__ void fps_kernel(const float* __restrict__ x,
                           const int* __restrict__ far1, const int* __restrict__ far2) {
    __shared__ float sxx[512], sxy[512], sxz[512];
    int which = blockIdx.x >> 7;
    int b = blockIdx.x & 127;
    int npoint = which ? 1000 : 500;
    int* out = (which ? g_idx2 : g_idx1) + b * npoint;
    int far = which ? far2[b] : far1[b];
    const float* xb = x + (size_t)b * NPT * 3;
    int lane = threadIdx.x;

    float px[16], py[16], pz[16], dist[16];
#pragma unroll
    for (int j = 0; j < 16; j++) {
        int p = j * 32 + lane;
        if (p < NPT) {
            px[j] = xb[p * 3]; py[j] = xb[p * 3 + 1]; pz[j] = xb[p * 3 + 2];
            dist[j] = 1e10f;
            sxx[p] = px[j]; sxy[p] = py[j]; sxz[p] = pz[j];
        } else {
            px[j] = 0.f; py[j] = 0.f; pz[j] = 0.f;
            dist[j] = -1.0f;
        }
    }
    __syncwarp();

    for (int t = 0; t < npoint; t++) {
        if (lane == 0) out[t] = far;
        if (t + 1 == npoint) break;
        float cx = sxx[far], cy = sxy[far], cz = sxz[far];
        float nd[16];
#pragma unroll
        for (int j = 0; j < 16; j++) {
            float dx = __fsub_rn(px[j], cx);
            float dy = __fsub_rn(py[j], cy);
            float dz = __fsub_rn(pz[j], cz);
            float d  = __fadd_rn(__fadd_rn(__fmul_rn(dx, dx), __fmul_rn(dy, dy)),
                                 __fmul_rn(dz, dz));
            nd[j] = fminf(dist[j], d);
            dist[j] = nd[j];
        }
        float m[8];
#pragma unroll
        for (int j = 0; j < 8; j++) m[j] = fmaxf(nd[2 * j], nd[2 * j + 1]);
#pragma unroll
        for (int j = 0; j < 4; j++) m[j] = fmaxf(m[j], m[j + 4]);
        m[0] = fmaxf(m[0], m[2]); m[1] = fmaxf(m[1], m[3]);
        float best = fmaxf(m[0], m[1]);
        unsigned mb = __reduce_max_sync(0xffffffffu, __float_as_uint(best));
        unsigned c[16];
#pragma unroll
        for (int j = 0; j < 16; j++)
            c[j] = (__float_as_uint(nd[j]) == mb) ? (unsigned)(j * 32 + lane) : 0xffffffffu;
#pragma unroll
        for (int j = 0; j < 8; j++) c[j] = min(c[j], c[j + 8]);
#pragma unroll
        for (int j = 0; j < 4; j++) c[j] = min(c[j], c[j + 4]);
        c[0] = min(c[0], c[2]); c[1] = min(c[1], c[3]);
        far = (int)__reduce_min_sync(0xffffffffu, min(c[0], c[1]));
    }
}

// ---------------- gathers (fp16 hi/lo, 16B chunks; zero K-pad) ----------------
__global__ void gather1b(const float* __restrict__ x) {
    int t = blockIdx.x * 256 + threadIdx.x;
    if (t >= NROWS * 33) return;
    int r = t / 33, c = t - r * 33;
    int b = r / 500;
    int i = g_idx1[r];
    size_t src = (size_t)b * 500 + i;
    size_t drow = (size_t)r * 264;
    if (c < 32) {
        *(uint4*)(g_hiQ + drow + c * 8) = *(const uint4*)(g_hiP + src * 256 + c * 8);
        *(uint4*)(g_loQ + drow + c * 8) = *(const uint4*)(g_loP + src * 256 + c * 8);
    } else {
        const float* xp = x + src * 3;
        __half h[8], l[8];
#pragma unroll
        for (int j = 0; j < 8; j++) { h[j] = __float2half(0.f); l[j] = h[j]; }
#pragma unroll
        for (int j = 0; j < 3; j++) {
            float v = xp[j];
            h[j] = __float2half_rn(v);
            l[j] = __float2half_rn(v - __half2float(h[j]));
        }
        *(uint4*)(g_hiQ + drow + 256) = *(uint4*)h;
        *(uint4*)(g_loQ + drow + 256) = *(uint4*)l;
    }
}
__global__ void gather2b(const float* __restrict__ x) {
    int t = blockIdx.x * 256 + threadIdx.x;
    if (t >= 128000 * 49) return;
    int r = t / 49, c = t - r * 49;
    int b = r / 1000;
    int i = g_idx2[r];
    size_t src = (size_t)b * 500 + i;
    size_t drow = (size_t)r * 392;
    if (c < 48) {
        *(uint4*)(g_hiQ + drow + c * 8) = *(const uint4*)(g_hiP + src * 384 + c * 8);
        *(uint4*)(g_loQ + drow + c * 8) = *(const uint4*)(g_loP + src * 384 + c * 8);
    } else {
        const float* xp = x + src * 3;
        __half h[8], l[8];
#pragma unroll
        for (int j = 0; j < 8; j++) { h[j] = __float2half(0.f); l[j] = h[j]; }
#pragma unroll
        for (int j = 0; j < 3; j++) {
            float v = xp[j];
            h[j] = __float2half_rn(v);
            l[j] = __float2half_rn(v - __half2float(h[j]));
        }
        *(uint4*)(g_hiQ + drow + 384) = *(uint4*)h;
        *(uint4*)(g_loQ + drow + 384) = *(uint4*)l;
    }
}

// ---------------- max-pool ----------------
__global__ void maxpool_kernel(const float* __restrict__ l8, float* __restrict__ out) {
    int t = blockIdx.x * 256 + threadIdx.x;
    if (t >= BATCH * 512) return;
    int b = t >> 9, c = t & 511;
    const float* p = l8 + (size_t)b * 1000 * 512 + c;
    float m = -1e30f;
#pragma unroll 4
    for (int i = 0; i < 1000; i++) m = fmaxf(m, p[(size_t)i * 512]);
    out[t] = m;
}

// ---------------- launch ----------------
extern "C" void kernel_launch(void* const* d_in, const int* in_sizes, int n_in,
                              void* d_out, int out_size) {
    const float* x     = (const float*)d_in[0];
    const float* confW = (const float*)d_in[1];
    const float* confb = (const float*)d_in[2];
    const float* w1    = (const float*)d_in[3];
    const float* b1    = (const float*)d_in[4];
    const float* w2    = (const float*)d_in[5];
    const float* b2    = (const float*)d_in[6];
    const float* pc1W  = (const float*)d_in[7];
    const float* pc1b  = (const float*)d_in[8];
    const float* w3    = (const float*)d_in[9];
    const float* b3    = (const float*)d_in[10];
    const float* w4    = (const float*)d_in[11];
    const float* b4    = (const float*)d_in[12];
    const float* pc2W  = (const float*)d_in[13];
    const float* pc2b  = (const float*)d_in[14];
    const float* w5    = (const float*)d_in[15];
    const float* b5    = (const float*)d_in[16];
    const float* w6    = (const float*)d_in[17];
    const float* b6    = (const float*)d_in[18];
    const int* far1    = (const int*)d_in[20];
    const int* far2    = (const int*)d_in[21];
    float* out = (float*)d_out;

    __half *hiP, *loP, *hiQ, *loQ, *wH;
    float* f32;
    cudaGetSymbolAddress((void**)&hiP, g_hiP);
    cudaGetSymbolAddress((void**)&loP, g_loP);
    cudaGetSymbolAddress((void**)&hiQ, g_hiQ);
    cudaGetSymbolAddress((void**)&loQ, g_loQ);
    cudaGetSymbolAddress((void**)&wH,  g_wH);
    cudaGetSymbolAddress((void**)&f32, g_f32);

    cudaFuncSetAttribute(gemm_f16, cudaFuncAttributeMaxDynamicSharedMemorySize, GEMM_SMEM);

    pack_w<<<(742400 + 255) / 256, 256>>>(w2, pc1W, w3, w4, pc2W, w5, w6);
    point_mlp1<<<(NROWS * 16 + 255) / 256, 256>>>(x, confW, confb, w1, b1);
    fps_kernel<<<256, 32>>>(x, far1, far2);

    // l2: (64000x256, K=64), relu
    gemm_f16<<<dim3(1, 500), 256, GEMM_SMEM>>>(hiP, loP, wH + OFF_W2,
        b2, nullptr, hiQ, loQ, NROWS, 256, 64, 1, 1);
    // l3: (64000x256, K=256)
    gemm_f16<<<dim3(1, 500), 256, GEMM_SMEM>>>(hiQ, loQ, wH + OFF_PC1,
        pc1b, nullptr, hiP, loP, NROWS, 256, 256, 0, 1);
    gather1b<<<(NROWS * 33 + 255) / 256, 256>>>(x);
    // l4: (64000x256, K=264), relu
    gemm_f16<<<dim3(1, 500), 256, GEMM_SMEM>>>(hiQ, loQ, wH + OFF_W3,
        b3, nullptr, hiP, loP, NROWS, 256, 264, 1, 1);
    // l5: (64000x384, K=256), relu
    gemm_f16<<<dim3(2, 500), 256, GEMM_SMEM>>>(hiP, loP, wH + OFF_W4,
        b4, nullptr, hiQ, loQ, NROWS, 384, 256, 1, 1);
    // l6: (64000x384, K=384)
    gemm_f16<<<dim3(2, 500), 256, GEMM_SMEM>>>(hiQ, loQ, wH + OFF_PC2,
        pc2b, nullptr, hiP, loP, NROWS, 384, 384, 0, 1);
    gather2b<<<(128000 * 49 + 255) / 256, 256>>>(x);
    // l7: (128000x384, K=392), relu
    gemm_f16<<<dim3(2, 1000), 256, GEMM_SMEM>>>(hiQ, loQ, wH + OFF_W5,
        b5, nullptr, hiP, loP, 128000, 384, 392, 1, 1);
    // l8: (128000x512, K=384), relu, fp32 out
    gemm_f16<<<dim3(2, 1000), 256, GEMM_SMEM>>>(hiP, loP, wH + OFF_W6,
        b6, f32, nullptr, nullptr, 128000, 512, 384, 1, 0);

    maxpool_kernel<<<(BATCH * 512 + 255) / 256, 256>>>(f32, out);
}

// round 6
// speedup vs baseline: 3.9406x; 3.9406x over previous
#include <cuda_runtime.h>
#include <cuda_fp16.h>
#include <math.h>
#include <cstdint>

#define BATCH 128
#define NPT   500
#define NROWS (BATCH*NPT)

typedef unsigned long long ull;

// ---------------- scratch (static; no allocation) ----------------
__device__ __align__(256) __half g_actP[52428800];
__device__ __align__(256) __half g_actQ[52428800];
__device__ __align__(256) float g_f32[65536000];
__device__ __align__(256) __half g_wH[742528];
__device__ __align__(256) int g_idx1[BATCH * 500];
__device__ __align__(256) int g_idx2[BATCH * 1000];

// weight arena offsets (elements, K padded to mult of 8)
#define OFF_W2   0
#define OFF_PC1  16384
#define OFF_W3   81920
#define OFF_W4   149504
#define OFF_PC2  247808
#define OFF_W5   395264
#define OFF_W6   545792

// ---------------- helpers ----------------
__device__ __forceinline__ uint32_t smem_u32(const void* p) {
    uint32_t a;
    asm("{ .reg .u64 t; cvta.to.shared.u64 t, %1; cvt.u32.u64 %0, t; }" : "=r"(a) : "l"(p));
    return a;
}
__device__ __forceinline__ void cpa16(uint32_t dst, const void* src, int sz) {
    asm volatile("cp.async.cg.shared.global [%0], [%1], 16, %2;"
        :: "r"(dst), "l"(src), "r"(sz) : "memory");
}
__device__ __forceinline__ void ldm_x4(uint32_t* r, uint32_t addr) {
    asm volatile("ldmatrix.sync.aligned.m8n8.x4.shared.b16 {%0,%1,%2,%3}, [%4];"
        : "=r"(r[0]), "=r"(r[1]), "=r"(r[2]), "=r"(r[3]) : "r"(addr));
}
__device__ __forceinline__ void ldm_x2(uint32_t& r0, uint32_t& r1, uint32_t addr) {
    asm volatile("ldmatrix.sync.aligned.m8n8.x2.shared.b16 {%0,%1}, [%2];"
        : "=r"(r0), "=r"(r1) : "r"(addr));
}
__device__ __forceinline__ void mma_f16(float* d, const uint32_t* a, uint32_t b0, uint32_t b1) {
    asm volatile("mma.sync.aligned.m16n8k16.row.col.f32.f16.f16.f32 "
        "{%0,%1,%2,%3}, {%4,%5,%6,%7}, {%8,%9}, {%0,%1,%2,%3};"
        : "+f"(d[0]), "+f"(d[1]), "+f"(d[2]), "+f"(d[3])
        : "r"(a[0]), "r"(a[1]), "r"(a[2]), "r"(a[3]), "r"(b0), "r"(b1));
}

// ---------------- plain fp16 HMMA GEMM ----------------
// C = relu?( sum_k A[m,k]*W[n,k] + bias[n] ), A/W fp16, fp32 accum.
// CTA 128x128x64-stage, 8 warps (2M x 4N), warp tile 64x32.
// 3-stage cp.async pipeline; stage = A 16K | W 16K = 32KB. 2 CTAs/SM.
#define NSTG 3
#define STG 32768
static const int GEMM_SMEM = NSTG * STG;

__device__ __forceinline__ void g_fill(
    const __half* __restrict__ A, const __half* __restrict__ W,
    int K, int row0, int col0, int s, int nst, uint32_t sb, int tid)
{
    if (s < nst) {
        int k0 = s << 6;
        uint32_t base = sb + (uint32_t)(s % NSTG) * STG;
#pragma unroll
        for (int i = 0; i < 4; i++) {
            int g = (i << 8) + tid;
            int r = g >> 3, c = g & 7;
            int kg = k0 + (c << 3);
            int ok = (kg < K) ? 16 : 0;
            uint32_t d = base + ((uint32_t)r << 7) + (((uint32_t)(c ^ (r & 7))) << 4);
            cpa16(d,         A + (size_t)(row0 + r) * K + kg, ok);
            cpa16(d + 16384, W + (size_t)(col0 + r) * K + kg, ok);
        }
    }
    asm volatile("cp.async.commit_group;" ::: "memory");
}

__global__ void __launch_bounds__(256, 2)
gemm_f16(const __half* __restrict__ A, const __half* __restrict__ W,
         const float* __restrict__ bias,
         float* __restrict__ Cf, __half* __restrict__ Ch,
         int M, int N, int K, int relu, int mode)
{
    extern __shared__ char smem[];
    uint32_t sb = smem_u32(smem);
    int tid = threadIdx.x, lane = tid & 31, wid = tid >> 5;
    int warp_m = wid & 1;        // 64 rows
    int warp_n = wid >> 1;       // 32 cols
    int row0 = blockIdx.y << 7;
    int col0 = blockIdx.x << 7;
    int nst = (K + 63) >> 6;

    float acc[4][4][4];
#pragma unroll
    for (int a = 0; a < 4; a++)
#pragma unroll
        for (int b = 0; b < 4; b++)
#pragma unroll
            for (int c = 0; c < 4; c++) acc[a][b][c] = 0.f;

    g_fill(A, W, K, row0, col0, 0, nst, sb, tid);
    g_fill(A, W, K, row0, col0, 1, nst, sb, tid);

    int a_row = warp_m * 64 + (lane & 15);
    int a_sel = lane >> 4;
    int b_row = warp_n * 32 + (lane & 7);
    int b_sel = (lane >> 3) & 1;

    for (int s = 0; s < nst; s++) {
        asm volatile("cp.async.wait_group 1;" ::: "memory");
        __syncthreads();
        uint32_t base = sb + (uint32_t)(s % NSTG) * STG;
        int kr = K - (s << 6);
        int kcnt = (kr + 15) >> 4; if (kcnt > 4) kcnt = 4;
        for (int ks = 0; ks < kcnt; ks++) {
            uint32_t Fa[4][4];
            int ch_a = (ks << 1) + a_sel;
#pragma unroll
            for (int mi = 0; mi < 4; mi++) {
                int rr = a_row + mi * 16;
                ldm_x4(Fa[mi], base + ((uint32_t)rr << 7) + (((uint32_t)(ch_a ^ (rr & 7))) << 4));
            }
            int ch_b = (ks << 1) + b_sel;
#pragma unroll
            for (int ni = 0; ni < 4; ni++) {
                int nr = b_row + ni * 8;
                uint32_t b0, b1;
                ldm_x2(b0, b1, base + 16384 + ((uint32_t)nr << 7)
                              + (((uint32_t)(ch_b ^ (nr & 7))) << 4));
#pragma unroll
                for (int mi = 0; mi < 4; mi++)
                    mma_f16(acc[mi][ni], Fa[mi], b0, b1);
            }
        }
        g_fill(A, W, K, row0, col0, s + 2, nst, sb, tid);
    }

    // epilogue
    int er = row0 + warp_m * 64 + (lane >> 2);
    int ec = col0 + warp_n * 32 + ((lane & 3) << 1);
#pragma unroll
    for (int ni = 0; ni < 4; ni++) {
        int c = ec + ni * 8;
        float b0 = __ldg(bias + c), b1 = __ldg(bias + c + 1);
#pragma unroll
        for (int mi = 0; mi < 4; mi++) {
            int r = er + mi * 16;
            float v00 = acc[mi][ni][0] + b0, v01 = acc[mi][ni][1] + b1;
            float v10 = acc[mi][ni][2] + b0, v11 = acc[mi][ni][3] + b1;
            if (relu) {
                v00 = fmaxf(v00, 0.f); v01 = fmaxf(v01, 0.f);
                v10 = fmaxf(v10, 0.f); v11 = fmaxf(v11, 0.f);
            }
            if (mode == 0) {
                *(float2*)(Cf + (size_t)r * N + c)       = make_float2(v00, v01);
                *(float2*)(Cf + (size_t)(r + 8) * N + c) = make_float2(v10, v11);
            } else {
                __half2 h0 = __floats2half2_rn(v00, v01);
                __half2 h1 = __floats2half2_rn(v10, v11);
                *(__half2*)(Ch + (size_t)r * N + c)       = h0;
                *(__half2*)(Ch + (size_t)(r + 8) * N + c) = h1;
            }
        }
    }
}

// ---------------- weight pack (fp32 -> fp16, pad K) ----------------
__global__ void pack_w(const float* __restrict__ w2, const float* __restrict__ pc1,
                       const float* __restrict__ w3, const float* __restrict__ w4,
                       const float* __restrict__ pc2, const float* __restrict__ w5,
                       const float* __restrict__ w6) {
    int t = blockIdx.x * 256 + threadIdx.x;
    if (t >= 742400) return;
    float v;
    if (t < 81920) {
        v = (t < 16384) ? w2[t] : pc1[t - 16384];
    } else if (t < 149504) {
        int i = t - 81920; int r = i / 264, c = i - r * 264;
        v = (c < 259) ? w3[r * 259 + c] : 0.f;
    } else if (t < 247808) {
        v = w4[t - 149504];
    } else if (t < 395264) {
        v = pc2[t - 247808];
    } else if (t < 545792) {
        int i = t - 395264; int r = i / 392, c = i - r * 392;
        v = (c < 387) ? w5[r * 387 + c] : 0.f;
    } else {
        v = w6[t - 545792];
    }
    g_wH[t] = __float2half_rn(v);
}

// ---------------- fused conf + concat + first linear -> fp16 ----------------
__global__ void point_mlp1(const float* __restrict__ x,
                           const float* __restrict__ confW, const float* __restrict__ confb,
                           const float* __restrict__ w1, const float* __restrict__ b1) {
    int t = blockIdx.x * 256 + threadIdx.x;
    if (t >= NROWS * 16) return;
    int p = t >> 4, g = t & 15;
    float x0 = x[p * 3], x1 = x[p * 3 + 1], x2 = x[p * 3 + 2];
    float s = confW[0] * x0 + confW[1] * x1 + confW[2] * x2 + confb[0];
    float conf = 1.f / (1.f + expf(-s));
    const float* wr = w1 + (g * 4) * 4;
    float v[4];
#pragma unroll
    for (int r = 0; r < 4; r++) {
        float a = b1[g * 4 + r]
                + wr[r * 4 + 0] * conf + wr[r * 4 + 1] * x0
                + wr[r * 4 + 2] * x1   + wr[r * 4 + 3] * x2;
        v[r] = fmaxf(a, 0.f);
    }
    __half2 h0 = __floats2half2_rn(v[0], v[1]);
    __half2 h1 = __floats2half2_rn(v[2], v[3]);
    size_t o = (size_t)p * 64 + g * 4;
    *(__half2*)(g_actP + o)     = h0;
    *(__half2*)(g_actP + o + 2) = h1;
}

// ---------------- farthest point sampling (bitwise-matches XLA) ----------------
__global__ void fps_kernel(const float* __restrict__ x,
                           const int* __restrict__ far1, const int* __restrict__ far2) {
    __shared__ float sxx[512], sxy[512], sxz[512];
    int which = blockIdx.x >> 7;
    int b = blockIdx.x & 127;
    int npoint = which ? 1000 : 500;
    int* out = (which ? g_idx2 : g_idx1) + b * npoint;
    int far = which ? far2[b] : far1[b];
    const float* xb = x + (size_t)b * NPT * 3;
    int lane = threadIdx.x;

    float px[16], py[16], pz[16], dist[16];
#pragma unroll
    for (int j = 0; j < 16; j++) {
        int p = j * 32 + lane;
        if (p < NPT) {
            px[j] = xb[p * 3]; py[j] = xb[p * 3 + 1]; pz[j] = xb[p * 3 + 2];
            dist[j] = 1e10f;
            sxx[p] = px[j]; sxy[p] = py[j]; sxz[p] = pz[j];
        } else {
            px[j] = 0.f; py[j] = 0.f; pz[j] = 0.f;
            dist[j] = -1.0f;
        }
    }
    __syncwarp();

    for (int t = 0; t < npoint; t++) {
        if (lane == 0) out[t] = far;
        if (t + 1 == npoint) break;
        float cx = sxx[far], cy = sxy[far], cz = sxz[far];
        float nd[16];
#pragma unroll
        for (int j = 0; j < 16; j++) {
            float dx = __fsub_rn(px[j], cx);
            float dy = __fsub_rn(py[j], cy);
            float dz = __fsub_rn(pz[j], cz);
            float d  = __fadd_rn(__fadd_rn(__fmul_rn(dx, dx), __fmul_rn(dy, dy)),
                                 __fmul_rn(dz, dz));
            nd[j] = fminf(dist[j], d);
            dist[j] = nd[j];
        }
        float m[8];
#pragma unroll
        for (int j = 0; j < 8; j++) m[j] = fmaxf(nd[2 * j], nd[2 * j + 1]);
#pragma unroll
        for (int j = 0; j < 4; j++) m[j] = fmaxf(m[j], m[j + 4]);
        m[0] = fmaxf(m[0], m[2]); m[1] = fmaxf(m[1], m[3]);
        float best = fmaxf(m[0], m[1]);
        unsigned mb = __reduce_max_sync(0xffffffffu, __float_as_uint(best));
        unsigned c[16];
#pragma unroll
        for (int j = 0; j < 16; j++)
            c[j] = (__float_as_uint(nd[j]) == mb) ? (unsigned)(j * 32 + lane) : 0xffffffffu;
#pragma unroll
        for (int j = 0; j < 8; j++) c[j] = min(c[j], c[j + 8]);
#pragma unroll
        for (int j = 0; j < 4; j++) c[j] = min(c[j], c[j + 4]);
        c[0] = min(c[0], c[2]); c[1] = min(c[1], c[3]);
        far = (int)__reduce_min_sync(0xffffffffu, min(c[0], c[1]));
    }
}

// ---------------- gathers (fp16, 16B chunks; zero K-pad) ----------------
__global__ void gather1b(const float* __restrict__ x) {
    int t = blockIdx.x * 256 + threadIdx.x;
    if (t >= NROWS * 33) return;
    int r = t / 33, c = t - r * 33;
    int b = r / 500;
    int i = g_idx1[r];
    size_t src = (size_t)b * 500 + i;
    size_t drow = (size_t)r * 264;
    if (c < 32) {
        *(uint4*)(g_actQ + drow + c * 8) = *(const uint4*)(g_actP + src * 256 + c * 8);
    } else {
        const float* xp = x + src * 3;
        __half h[8];
#pragma unroll
        for (int j = 0; j < 8; j++) h[j] = __float2half(0.f);
#pragma unroll
        for (int j = 0; j < 3; j++) h[j] = __float2half_rn(xp[j]);
        *(uint4*)(g_actQ + drow + 256) = *(uint4*)h;
    }
}
__global__ void gather2b(const float* __restrict__ x) {
    int t = blockIdx.x * 256 + threadIdx.x;
    if (t >= 128000 * 49) return;
    int r = t / 49, c = t - r * 49;
    int b = r / 1000;
    int i = g_idx2[r];
    size_t src = (size_t)b * 500 + i;
    size_t drow = (size_t)r * 392;
    if (c < 48) {
        *(uint4*)(g_actQ + drow + c * 8) = *(const uint4*)(g_actP + src * 384 + c * 8);
    } else {
        const float* xp = x + src * 3;
        __half h[8];
#pragma unroll
        for (int j = 0; j < 8; j++) h[j] = __float2half(0.f);
#pragma unroll
        for (int j = 0; j < 3; j++) h[j] = __float2half_rn(xp[j]);
        *(uint4*)(g_actQ + drow + 384) = *(uint4*)h;
    }
}

// ---------------- max-pool ----------------
__global__ void maxpool_kernel(const float* __restrict__ l8, float* __restrict__ out) {
    int t = blockIdx.x * 256 + threadIdx.x;
    if (t >= BATCH * 512) return;
    int b = t >> 9, c = t & 511;
    const float* p = l8 + (size_t)b * 1000 * 512 + c;
    float m = -1e30f;
#pragma unroll 4
    for (int i = 0; i < 1000; i++) m = fmaxf(m, p[(size_t)i * 512]);
    out[t] = m;
}

// ---------------- launch ----------------
extern "C" void kernel_launch(void* const* d_in, const int* in_sizes, int n_in,
                              void* d_out, int out_size) {
    const float* x     = (const float*)d_in[0];
    const float* confW = (const float*)d_in[1];
    const float* confb = (const float*)d_in[2];
    const float* w1    = (const float*)d_in[3];
    const float* b1    = (const float*)d_in[4];
    const float* w2    = (const float*)d_in[5];
    const float* b2    = (const float*)d_in[6];
    const float* pc1W  = (const float*)d_in[7];
    const float* pc1b  = (const float*)d_in[8];
    const float* w3    = (const float*)d_in[9];
    const float* b3    = (const float*)d_in[10];
    const float* w4    = (const float*)d_in[11];
    const float* b4    = (const float*)d_in[12];
    const float* pc2W  = (const float*)d_in[13];
    const float* pc2b  = (const float*)d_in[14];
    const float* w5    = (const float*)d_in[15];
    const float* b5    = (const float*)d_in[16];
    const float* w6    = (const float*)d_in[17];
    const float* b6    = (const float*)d_in[18];
    const int* far1    = (const int*)d_in[20];
    const int* far2    = (const int*)d_in[21];
    float* out = (float*)d_out;

    __half *actP, *actQ, *wH;
    float* f32;
    cudaGetSymbolAddress((void**)&actP, g_actP);
    cudaGetSymbolAddress((void**)&actQ, g_actQ);
    cudaGetSymbolAddress((void**)&wH,   g_wH);
    cudaGetSymbolAddress((void**)&f32,  g_f32);

    cudaFuncSetAttribute(gemm_f16, cudaFuncAttributeMaxDynamicSharedMemorySize, GEMM_SMEM);

    pack_w<<<(742400 + 255) / 256, 256>>>(w2, pc1W, w3, w4, pc2W, w5, w6);
    point_mlp1<<<(NROWS * 16 + 255) / 256, 256>>>(x, confW, confb, w1, b1);
    fps_kernel<<<256, 32>>>(x, far1, far2);

    // l2: (64000x256, K=64), relu
    gemm_f16<<<dim3(2, 500), 256, GEMM_SMEM>>>(actP, wH + OFF_W2,
        b2, nullptr, actQ, NROWS, 256, 64, 1, 1);
    // l3: (64000x256, K=256)
    gemm_f16<<<dim3(2, 500), 256, GEMM_SMEM>>>(actQ, wH + OFF_PC1,
        pc1b, nullptr, actP, NROWS, 256, 256, 0, 1);
    gather1b<<<(NROWS * 33 + 255) / 256, 256>>>(x);
    // l4: (64000x256, K=264), relu
    gemm_f16<<<dim3(2, 500), 256, GEMM_SMEM>>>(actQ, wH + OFF_W3,
        b3, nullptr, actP, NROWS, 256, 264, 1, 1);
    // l5: (64000x384, K=256), relu
    gemm_f16<<<dim3(3, 500), 256, GEMM_SMEM>>>(actP, wH + OFF_W4,
        b4, nullptr, actQ, NROWS, 384, 256, 1, 1);
    // l6: (64000x384, K=384)
    gemm_f16<<<dim3(3, 500), 256, GEMM_SMEM>>>(actQ, wH + OFF_PC2,
        pc2b, nullptr, actP, NROWS, 384, 384, 0, 1);
    gather2b<<<(128000 * 49 + 255) / 256, 256>>>(x);
    // l7: (128000x384, K=392), relu
    gemm_f16<<<dim3(3, 1000), 256, GEMM_SMEM>>>(actQ, wH + OFF_W5,
        b5, nullptr, actP, 128000, 384, 392, 1, 1);
    // l8: (128000x512, K=384), relu, fp32 out
    gemm_f16<<<dim3(4, 1000), 256, GEMM_SMEM>>>(actP, wH + OFF_W6,
        b6, f32, nullptr, 128000, 512, 384, 1, 0);

    maxpool_kernel<<<(BATCH * 512 + 255) / 256, 256>>>(f32, out);
}

// round 7
// speedup vs baseline: 5.1123x; 1.2973x over previous
#include <cuda_runtime.h>
#include <cuda_fp16.h>
#include <math.h>
#include <cstdint>

#define BATCH 128
#define NPT   500
#define NROWS (BATCH*NPT)

typedef unsigned long long ull;

// ---------------- scratch (static; no allocation) ----------------
__device__ __align__(256) __half g_actP[52428800];
__device__ __align__(256) __half g_actQ[52428800];
__device__ __align__(256) __half g_wH[742528];
__device__ __align__(256) int g_idx1[BATCH * 500];
__device__ __align__(256) int g_idx2[BATCH * 1000];

// weight arena offsets (elements, K padded to mult of 8)
#define OFF_W2   0
#define OFF_PC1  16384
#define OFF_W3   81920
#define OFF_W4   149504
#define OFF_PC2  247808
#define OFF_W5   395264
#define OFF_W6   545792

// ---------------- helpers ----------------
__device__ __forceinline__ uint32_t smem_u32(const void* p) {
    uint32_t a;
    asm("{ .reg .u64 t; cvta.to.shared.u64 t, %1; cvt.u32.u64 %0, t; }" : "=r"(a) : "l"(p));
    return a;
}
__device__ __forceinline__ void cpa16(uint32_t dst, const void* src, int sz) {
    asm volatile("cp.async.cg.shared.global [%0], [%1], 16, %2;"
        :: "r"(dst), "l"(src), "r"(sz) : "memory");
}
__device__ __forceinline__ void ldm_x4(uint32_t* r, uint32_t addr) {
    asm volatile("ldmatrix.sync.aligned.m8n8.x4.shared.b16 {%0,%1,%2,%3}, [%4];"
        : "=r"(r[0]), "=r"(r[1]), "=r"(r[2]), "=r"(r[3]) : "r"(addr));
}
__device__ __forceinline__ void mma_f16(float* d, const uint32_t* a, uint32_t b0, uint32_t b1) {
    asm volatile("mma.sync.aligned.m16n8k16.row.col.f32.f16.f16.f32 "
        "{%0,%1,%2,%3}, {%4,%5,%6,%7}, {%8,%9}, {%0,%1,%2,%3};"
        : "+f"(d[0]), "+f"(d[1]), "+f"(d[2]), "+f"(d[3])
        : "r"(a[0]), "r"(a[1]), "r"(a[2]), "r"(a[3]), "r"(b0), "r"(b1));
}

// ---------------- plain fp16 HMMA GEMM ----------------
// C = relu?( sum_k A[m,k]*W[n,k] + bias[n] ), A/W fp16, fp32 accum.
// CTA 128x128x64-stage, 8 warps (2M x 4N), warp tile 64x32.
// 3-stage cp.async pipeline; stage = A 16K | W 16K = 32KB. 2 CTAs/SM.
// mode: 0 = fp32 C, 1 = fp16 C, 2 = fused per-batch column max into Cf
//       (M organized as batches of 1000 rows; relu must be on; no C written)
#define NSTG 3
#define STG 32768
static const int GEMM_SMEM = NSTG * STG;

__device__ __forceinline__ void g_fill(
    const __half* __restrict__ A, const __half* __restrict__ W,
    int K, int row0, int col0, int s, int nst, uint32_t sb, int tid)
{
    if (s < nst) {
        int k0 = s << 6;
        uint32_t base = sb + (uint32_t)(s % NSTG) * STG;
#pragma unroll
        for (int i = 0; i < 4; i++) {
            int g = (i << 8) + tid;
            int r = g >> 3, c = g & 7;
            int kg = k0 + (c << 3);
            int ok = (kg < K) ? 16 : 0;
            uint32_t d = base + ((uint32_t)r << 7) + (((uint32_t)(c ^ (r & 7))) << 4);
            cpa16(d,         A + (size_t)(row0 + r) * K + kg, ok);
            cpa16(d + 16384, W + (size_t)(col0 + r) * K + kg, ok);
        }
    }
    asm volatile("cp.async.commit_group;" ::: "memory");
}

__global__ void __launch_bounds__(256, 2)
gemm_f16(const __half* __restrict__ A, const __half* __restrict__ W,
         const float* __restrict__ bias,
         float* __restrict__ Cf, __half* __restrict__ Ch,
         int M, int N, int K, int relu, int mode)
{
    extern __shared__ char smem[];
    uint32_t sb = smem_u32(smem);
    int tid = threadIdx.x, lane = tid & 31, wid = tid >> 5;
    int warp_m = wid & 1;        // 64 rows
    int warp_n = wid >> 1;       // 32 cols
    int row0 = blockIdx.y << 7;
    int col0 = blockIdx.x << 7;
    int nst = (K + 63) >> 6;

    float acc[4][4][4];
#pragma unroll
    for (int a = 0; a < 4; a++)
#pragma unroll
        for (int b = 0; b < 4; b++)
#pragma unroll
            for (int c = 0; c < 4; c++) acc[a][b][c] = 0.f;

    g_fill(A, W, K, row0, col0, 0, nst, sb, tid);
    g_fill(A, W, K, row0, col0, 1, nst, sb, tid);

    int a_row = warp_m * 64 + (lane & 15);
    int a_sel = lane >> 4;
    // B via x4: lanes 0-7 -> (ni, k-lo), 8-15 -> (ni, k-hi), 16-23 -> (ni+1, k-lo), 24-31 -> (ni+1, k-hi)
    int b_row4 = warp_n * 32 + ((lane >> 4) << 3) + (lane & 7);
    int b_ksel = (lane >> 3) & 1;

    for (int s = 0; s < nst; s++) {
        asm volatile("cp.async.wait_group 1;" ::: "memory");
        __syncthreads();
        uint32_t base = sb + (uint32_t)(s % NSTG) * STG;
        int kr = K - (s << 6);
        int kcnt = (kr + 15) >> 4; if (kcnt > 4) kcnt = 4;
        for (int ks = 0; ks < kcnt; ks++) {
            uint32_t Fa[4][4];
            int ch_a = (ks << 1) + a_sel;
#pragma unroll
            for (int mi = 0; mi < 4; mi++) {
                int rr = a_row + mi * 16;
                ldm_x4(Fa[mi], base + ((uint32_t)rr << 7) + (((uint32_t)(ch_a ^ (rr & 7))) << 4));
            }
            int ch_b = (ks << 1) + b_ksel;
#pragma unroll
            for (int np = 0; np < 2; np++) {
                int nr = b_row4 + np * 16;
                uint32_t B4[4];
                ldm_x4(B4, base + 16384 + ((uint32_t)nr << 7)
                           + (((uint32_t)(ch_b ^ (nr & 7))) << 4));
#pragma unroll
                for (int mi = 0; mi < 4; mi++) {
                    mma_f16(acc[mi][np * 2],     Fa[mi], B4[0], B4[1]);
                    mma_f16(acc[mi][np * 2 + 1], Fa[mi], B4[2], B4[3]);
                }
            }
        }
        g_fill(A, W, K, row0, col0, s + 2, nst, sb, tid);
    }

    // epilogue
    int er = row0 + warp_m * 64 + (lane >> 2);
    int ec = col0 + warp_n * 32 + ((lane & 3) << 1);
    if (mode != 2) {
#pragma unroll
        for (int ni = 0; ni < 4; ni++) {
            int c = ec + ni * 8;
            float b0 = __ldg(bias + c), b1 = __ldg(bias + c + 1);
#pragma unroll
            for (int mi = 0; mi < 4; mi++) {
                int r = er + mi * 16;
                float v00 = acc[mi][ni][0] + b0, v01 = acc[mi][ni][1] + b1;
                float v10 = acc[mi][ni][2] + b0, v11 = acc[mi][ni][3] + b1;
                if (relu) {
                    v00 = fmaxf(v00, 0.f); v01 = fmaxf(v01, 0.f);
                    v10 = fmaxf(v10, 0.f); v11 = fmaxf(v11, 0.f);
                }
                if (mode == 0) {
                    *(float2*)(Cf + (size_t)r * N + c)       = make_float2(v00, v01);
                    *(float2*)(Cf + (size_t)(r + 8) * N + c) = make_float2(v10, v11);
                } else {
                    *(__half2*)(Ch + (size_t)r * N + c)       = __floats2half2_rn(v00, v01);
                    *(__half2*)(Ch + (size_t)(r + 8) * N + c) = __floats2half2_rn(v10, v11);
                }
            }
        }
    } else {
        // fused per-batch (1000 rows) column max -> Cf[batch][N] via atomicMax.
        // All values relu'd (>=0) so 0 is the identity and int-compare == float-compare.
        int bat0 = row0 / 1000;
        int cut = (bat0 + 1) * 1000;
        bool has2 = (row0 + 127 >= cut);
        int* outI = (int*)Cf;
#pragma unroll
        for (int ni = 0; ni < 4; ni++) {
            int c = ec + ni * 8;
            float b0 = __ldg(bias + c), b1 = __ldg(bias + c + 1);
            float s00 = 0.f, s01 = 0.f, s10 = 0.f, s11 = 0.f;
#pragma unroll
            for (int mi = 0; mi < 4; mi++) {
                int r = er + mi * 16;
                float v00 = fmaxf(acc[mi][ni][0] + b0, 0.f);
                float v01 = fmaxf(acc[mi][ni][1] + b1, 0.f);
                float v10 = fmaxf(acc[mi][ni][2] + b0, 0.f);
                float v11 = fmaxf(acc[mi][ni][3] + b1, 0.f);
                if (r < cut)     { s00 = fmaxf(s00, v00); s01 = fmaxf(s01, v01); }
                else             { s10 = fmaxf(s10, v00); s11 = fmaxf(s11, v01); }
                if (r + 8 < cut) { s00 = fmaxf(s00, v10); s01 = fmaxf(s01, v11); }
                else             { s10 = fmaxf(s10, v10); s11 = fmaxf(s11, v11); }
            }
#pragma unroll
            for (int d = 4; d <= 16; d <<= 1) {
                s00 = fmaxf(s00, __shfl_xor_sync(0xffffffffu, s00, d));
                s01 = fmaxf(s01, __shfl_xor_sync(0xffffffffu, s01, d));
                s10 = fmaxf(s10, __shfl_xor_sync(0xffffffffu, s10, d));
                s11 = fmaxf(s11, __shfl_xor_sync(0xffffffffu, s11, d));
            }
            if ((lane >> 2) == 0) {
                atomicMax(outI + bat0 * N + c,     __float_as_int(s00));
                atomicMax(outI + bat0 * N + c + 1, __float_as_int(s01));
                if (has2) {
                    atomicMax(outI + (bat0 + 1) * N + c,     __float_as_int(s10));
                    atomicMax(outI + (bat0 + 1) * N + c + 1, __float_as_int(s11));
                }
            }
        }
    }
}

// ---------------- out init (relu output >= 0, so 0 is the max identity) ----------------
__global__ void init_out(float* __restrict__ out) {
    int t = blockIdx.x * 256 + threadIdx.x;
    if (t < BATCH * 512) out[t] = 0.f;
}

// ---------------- weight pack (fp32 -> fp16, pad K) ----------------
__global__ void pack_w(const float* __restrict__ w2, const float* __restrict__ pc1,
                       const float* __restrict__ w3, const float* __restrict__ w4,
                       const float* __restrict__ pc2, const float* __restrict__ w5,
                       const float* __restrict__ w6) {
    int t = blockIdx.x * 256 + threadIdx.x;
    if (t >= 742400) return;
    float v;
    if (t < 81920) {
        v = (t < 16384) ? w2[t] : pc1[t - 16384];
    } else if (t < 149504) {
        int i = t - 81920; int r = i / 264, c = i - r * 264;
        v = (c < 259) ? w3[r * 259 + c] : 0.f;
    } else if (t < 247808) {
        v = w4[t - 149504];
    } else if (t < 395264) {
        v = pc2[t - 247808];
    } else if (t < 545792) {
        int i = t - 395264; int r = i / 392, c = i - r * 392;
        v = (c < 387) ? w5[r * 387 + c] : 0.f;
    } else {
        v = w6[t - 545792];
    }
    g_wH[t] = __float2half_rn(v);
}

// ---------------- fused conf + concat + first linear -> fp16 ----------------
__global__ void point_mlp1(const float* __restrict__ x,
                           const float* __restrict__ confW, const float* __restrict__ confb,
                           const float* __restrict__ w1, const float* __restrict__ b1) {
    int t = blockIdx.x * 256 + threadIdx.x;
    if (t >= NROWS * 16) return;
    int p = t >> 4, g = t & 15;
    float x0 = x[p * 3], x1 = x[p * 3 + 1], x2 = x[p * 3 + 2];
    float s = confW[0] * x0 + confW[1] * x1 + confW[2] * x2 + confb[0];
    float conf = 1.f / (1.f + expf(-s));
    const float* wr = w1 + (g * 4) * 4;
    float v[4];
#pragma unroll
    for (int r = 0; r < 4; r++) {
        float a = b1[g * 4 + r]
                + wr[r * 4 + 0] * conf + wr[r * 4 + 1] * x0
                + wr[r * 4 + 2] * x1   + wr[r * 4 + 3] * x2;
        v[r] = fmaxf(a, 0.f);
    }
    __half2 h0 = __floats2half2_rn(v[0], v[1]);
    __half2 h1 = __floats2half2_rn(v[2], v[3]);
    size_t o = (size_t)p * 64 + g * 4;
    *(__half2*)(g_actP + o)     = h0;
    *(__half2*)(g_actP + o + 2) = h1;
}

// ---------------- farthest point sampling (bitwise-matches XLA) ----------------
__global__ void fps_kernel(const float* __restrict__ x,
                           const int* __restrict__ far1, const int* __restrict__ far2) {
    __shared__ float sxx[512], sxy[512], sxz[512];
    int which = blockIdx.x >> 7;
    int b = blockIdx.x & 127;
    int npoint = which ? 1000 : 500;
    int* out = (which ? g_idx2 : g_idx1) + b * npoint;
    int far = which ? far2[b] : far1[b];
    const float* xb = x + (size_t)b * NPT * 3;
    int lane = threadIdx.x;

    float px[16], py[16], pz[16], dist[16];
#pragma unroll
    for (int j = 0; j < 16; j++) {
        int p = j * 32 + lane;
        if (p < NPT) {
            px[j] = xb[p * 3]; py[j] = xb[p * 3 + 1]; pz[j] = xb[p * 3 + 2];
            dist[j] = 1e10f;
            sxx[p] = px[j]; sxy[p] = py[j]; sxz[p] = pz[j];
        } else {
            px[j] = 0.f; py[j] = 0.f; pz[j] = 0.f;
            dist[j] = -1.0f;
        }
    }
    __syncwarp();

    for (int t = 0; t < npoint; t++) {
        if (lane == 0) out[t] = far;
        if (t + 1 == npoint) break;
        float cx = sxx[far], cy = sxy[far], cz = sxz[far];
        float nd[16];
#pragma unroll
        for (int j = 0; j < 16; j++) {
            float dx = __fsub_rn(px[j], cx);
            float dy = __fsub_rn(py[j], cy);
            float dz = __fsub_rn(pz[j], cz);
            float d  = __fadd_rn(__fadd_rn(__fmul_rn(dx, dx), __fmul_rn(dy, dy)),
                                 __fmul_rn(dz, dz));
            nd[j] = fminf(dist[j], d);
            dist[j] = nd[j];
        }
        float m[8];
#pragma unroll
        for (int j = 0; j < 8; j++) m[j] = fmaxf(nd[2 * j], nd[2 * j + 1]);
#pragma unroll
        for (int j = 0; j < 4; j++) m[j] = fmaxf(m[j], m[j + 4]);
        m[0] = fmaxf(m[0], m[2]); m[1] = fmaxf(m[1], m[3]);
        float best = fmaxf(m[0], m[1]);
        unsigned mb = __reduce_max_sync(0xffffffffu, __float_as_uint(best));
        unsigned c[16];
#pragma unroll
        for (int j = 0; j < 16; j++)
            c[j] = (__float_as_uint(nd[j]) == mb) ? (unsigned)(j * 32 + lane) : 0xffffffffu;
#pragma unroll
        for (int j = 0; j < 8; j++) c[j] = min(c[j], c[j + 8]);
#pragma unroll
        for (int j = 0; j < 4; j++) c[j] = min(c[j], c[j + 4]);
        c[0] = min(c[0], c[2]); c[1] = min(c[1], c[3]);
        far = (int)__reduce_min_sync(0xffffffffu, min(c[0], c[1]));
    }
}

// ---------------- gathers (fp16, 16B chunks; zero K-pad) ----------------
__global__ void gather1b(const float* __restrict__ x) {
    int t = blockIdx.x * 256 + threadIdx.x;
    if (t >= NROWS * 33) return;
    int r = t / 33, c = t - r * 33;
    int b = r / 500;
    int i = g_idx1[r];
    size_t src = (size_t)b * 500 + i;
    size_t drow = (size_t)r * 264;
    if (c < 32) {
        *(uint4*)(g_actQ + drow + c * 8) = *(const uint4*)(g_actP + src * 256 + c * 8);
    } else {
        const float* xp = x + src * 3;
        __half h[8];
#pragma unroll
        for (int j = 0; j < 8; j++) h[j] = __float2half(0.f);
#pragma unroll
        for (int j = 0; j < 3; j++) h[j] = __float2half_rn(xp[j]);
        *(uint4*)(g_actQ + drow + 256) = *(uint4*)h;
    }
}
__global__ void gather2b(const float* __restrict__ x) {
    int t = blockIdx.x * 256 + threadIdx.x;
    if (t >= 128000 * 49) return;
    int r = t / 49, c = t - r * 49;
    int b = r / 1000;
    int i = g_idx2[r];
    size_t src = (size_t)b * 500 + i;
    size_t drow = (size_t)r * 392;
    if (c < 48) {
        *(uint4*)(g_actQ + drow + c * 8) = *(const uint4*)(g_actP + src * 384 + c * 8);
    } else {
        const float* xp = x + src * 3;
        __half h[8];
#pragma unroll
        for (int j = 0; j < 8; j++) h[j] = __float2half(0.f);
#pragma unroll
        for (int j = 0; j < 3; j++) h[j] = __float2half_rn(xp[j]);
        *(uint4*)(g_actQ + drow + 384) = *(uint4*)h;
    }
}

// ---------------- launch ----------------
extern "C" void kernel_launch(void* const* d_in, const int* in_sizes, int n_in,
                              void* d_out, int out_size) {
    const float* x     = (const float*)d_in[0];
    const float* confW = (const float*)d_in[1];
    const float* confb = (const float*)d_in[2];
    const float* w1    = (const float*)d_in[3];
    const float* b1    = (const float*)d_in[4];
    const float* w2    = (const float*)d_in[5];
    const float* b2    = (const float*)d_in[6];
    const float* pc1W  = (const float*)d_in[7];
    const float* pc1b  = (const float*)d_in[8];
    const float* w3    = (const float*)d_in[9];
    const float* b3    = (const float*)d_in[10];
    const float* w4    = (const float*)d_in[11];
    const float* b4    = (const float*)d_in[12];
    const float* pc2W  = (const float*)d_in[13];
    const float* pc2b  = (const float*)d_in[14];
    const float* w5    = (const float*)d_in[15];
    const float* b5    = (const float*)d_in[16];
    const float* w6    = (const float*)d_in[17];
    const float* b6    = (const float*)d_in[18];
    const int* far1    = (const int*)d_in[20];
    const int* far2    = (const int*)d_in[21];
    float* out = (float*)d_out;

    __half *actP, *actQ, *wH;
    cudaGetSymbolAddress((void**)&actP, g_actP);
    cudaGetSymbolAddress((void**)&actQ, g_actQ);
    cudaGetSymbolAddress((void**)&wH,   g_wH);

    cudaFuncSetAttribute(gemm_f16, cudaFuncAttributeMaxDynamicSharedMemorySize, GEMM_SMEM);

    // one-time host resources for the FPS side stream (host-side only; no device mem)
    static cudaStream_t s1 = nullptr;
    static cudaEvent_t evA = nullptr, evB = nullptr;
    if (s1 == nullptr) {
        cudaStreamCreateWithFlags(&s1, cudaStreamNonBlocking);
        cudaEventCreateWithFlags(&evA, cudaEventDisableTiming);
        cudaEventCreateWithFlags(&evB, cudaEventDisableTiming);
    }

    init_out<<<(BATCH * 512 + 255) / 256, 256>>>(out);

    // fork: FPS runs on s1 concurrently with weight pack + first GEMMs
    cudaEventRecord(evA, 0);
    cudaStreamWaitEvent(s1, evA, 0);
    fps_kernel<<<256, 32, 0, s1>>>(x, far1, far2);
    cudaEventRecord(evB, s1);

    pack_w<<<(742400 + 255) / 256, 256>>>(w2, pc1W, w3, w4, pc2W, w5, w6);
    point_mlp1<<<(NROWS * 16 + 255) / 256, 256>>>(x, confW, confb, w1, b1);

    // l2: (64000x256, K=64), relu
    gemm_f16<<<dim3(2, 500), 256, GEMM_SMEM>>>(actP, wH + OFF_W2,
        b2, nullptr, actQ, NROWS, 256, 64, 1, 1);
    // l3: (64000x256, K=256)
    gemm_f16<<<dim3(2, 500), 256, GEMM_SMEM>>>(actQ, wH + OFF_PC1,
        pc1b, nullptr, actP, NROWS, 256, 256, 0, 1);

    // join: gathers need FPS indices
    cudaStreamWaitEvent(0, evB, 0);

    gather1b<<<(NROWS * 33 + 255) / 256, 256>>>(x);
    // l4: (64000x256, K=264), relu
    gemm_f16<<<dim3(2, 500), 256, GEMM_SMEM>>>(actQ, wH + OFF_W3,
        b3, nullptr, actP, NROWS, 256, 264, 1, 1);
    // l5: (64000x384, K=256), relu
    gemm_f16<<<dim3(3, 500), 256, GEMM_SMEM>>>(actP, wH + OFF_W4,
        b4, nullptr, actQ, NROWS, 384, 256, 1, 1);
    // l6: (64000x384, K=384)
    gemm_f16<<<dim3(3, 500), 256, GEMM_SMEM>>>(actQ, wH + OFF_PC2,
        pc2b, nullptr, actP, NROWS, 384, 384, 0, 1);
    gather2b<<<(128000 * 49 + 255) / 256, 256>>>(x);
    // l7: (128000x384, K=392), relu
    gemm_f16<<<dim3(3, 1000), 256, GEMM_SMEM>>>(actQ, wH + OFF_W5,
        b5, nullptr, actP, 128000, 384, 392, 1, 1);
    // l8: (128000x512, K=384), relu, FUSED max-pool -> out (no C store)
    gemm_f16<<<dim3(4, 1000), 256, GEMM_SMEM>>>(actP, wH + OFF_W6,
        b6, out, nullptr, 128000, 512, 384, 1, 2);
}

// round 8
// speedup vs baseline: 5.6181x; 1.0989x over previous
#include <cuda_runtime.h>
#include <cuda_fp16.h>
#include <math.h>
#include <cstdint>

#define BATCH 128
#define NPT   500
#define NROWS (BATCH*NPT)

typedef unsigned long long ull;

// ---------------- scratch (static; no allocation) ----------------
__device__ __align__(256) __half g_actP[52428800];
__device__ __align__(256) __half g_actQ[52428800];
__device__ __align__(256) __half g_wH[742528];
__device__ __align__(256) int g_idx1[BATCH * 500];
__device__ __align__(256) int g_idx2[BATCH * 1000];

// weight arena offsets (elements, K padded to mult of 8)
#define OFF_W2   0
#define OFF_PC1  16384
#define OFF_W3   81920
#define OFF_W4   149504
#define OFF_PC2  247808
#define OFF_W5   395264
#define OFF_W6   545792

// ---------------- helpers ----------------
__device__ __forceinline__ uint32_t smem_u32(const void* p) {
    uint32_t a;
    asm("{ .reg .u64 t; cvta.to.shared.u64 t, %1; cvt.u32.u64 %0, t; }" : "=r"(a) : "l"(p));
    return a;
}
__device__ __forceinline__ void cpa16(uint32_t dst, const void* src, int sz) {
    asm volatile("cp.async.cg.shared.global [%0], [%1], 16, %2;"
        :: "r"(dst), "l"(src), "r"(sz) : "memory");
}
__device__ __forceinline__ void ldm_x4(uint32_t* r, uint32_t addr) {
    asm volatile("ldmatrix.sync.aligned.m8n8.x4.shared.b16 {%0,%1,%2,%3}, [%4];"
        : "=r"(r[0]), "=r"(r[1]), "=r"(r[2]), "=r"(r[3]) : "r"(addr));
}
__device__ __forceinline__ void mma_f16(float* d, const uint32_t* a, uint32_t b0, uint32_t b1) {
    asm volatile("mma.sync.aligned.m16n8k16.row.col.f32.f16.f16.f32 "
        "{%0,%1,%2,%3}, {%4,%5,%6,%7}, {%8,%9}, {%0,%1,%2,%3};"
        : "+f"(d[0]), "+f"(d[1]), "+f"(d[2]), "+f"(d[3])
        : "r"(a[0]), "r"(a[1]), "r"(a[2]), "r"(a[3]), "r"(b0), "r"(b1));
}

// ---------------- plain fp16 HMMA GEMM (unchanged from R7) ----------------
#define NSTG 3
#define STG 32768
static const int GEMM_SMEM = NSTG * STG;

__device__ __forceinline__ void g_fill(
    const __half* __restrict__ A, const __half* __restrict__ W,
    int K, int row0, int col0, int s, int nst, uint32_t sb, int tid)
{
    if (s < nst) {
        int k0 = s << 6;
        uint32_t base = sb + (uint32_t)(s % NSTG) * STG;
#pragma unroll
        for (int i = 0; i < 4; i++) {
            int g = (i << 8) + tid;
            int r = g >> 3, c = g & 7;
            int kg = k0 + (c << 3);
            int ok = (kg < K) ? 16 : 0;
            uint32_t d = base + ((uint32_t)r << 7) + (((uint32_t)(c ^ (r & 7))) << 4);
            cpa16(d,         A + (size_t)(row0 + r) * K + kg, ok);
            cpa16(d + 16384, W + (size_t)(col0 + r) * K + kg, ok);
        }
    }
    asm volatile("cp.async.commit_group;" ::: "memory");
}

__global__ void __launch_bounds__(256, 2)
gemm_f16(const __half* __restrict__ A, const __half* __restrict__ W,
         const float* __restrict__ bias,
         float* __restrict__ Cf, __half* __restrict__ Ch,
         int M, int N, int K, int relu, int mode)
{
    extern __shared__ char smem[];
    uint32_t sb = smem_u32(smem);
    int tid = threadIdx.x, lane = tid & 31, wid = tid >> 5;
    int warp_m = wid & 1;
    int warp_n = wid >> 1;
    int row0 = blockIdx.y << 7;
    int col0 = blockIdx.x << 7;
    int nst = (K + 63) >> 6;

    float acc[4][4][4];
#pragma unroll
    for (int a = 0; a < 4; a++)
#pragma unroll
        for (int b = 0; b < 4; b++)
#pragma unroll
            for (int c = 0; c < 4; c++) acc[a][b][c] = 0.f;

    g_fill(A, W, K, row0, col0, 0, nst, sb, tid);
    g_fill(A, W, K, row0, col0, 1, nst, sb, tid);

    int a_row = warp_m * 64 + (lane & 15);
    int a_sel = lane >> 4;
    int b_row4 = warp_n * 32 + ((lane >> 4) << 3) + (lane & 7);
    int b_ksel = (lane >> 3) & 1;

    for (int s = 0; s < nst; s++) {
        asm volatile("cp.async.wait_group 1;" ::: "memory");
        __syncthreads();
        uint32_t base = sb + (uint32_t)(s % NSTG) * STG;
        int kr = K - (s << 6);
        int kcnt = (kr + 15) >> 4; if (kcnt > 4) kcnt = 4;
        for (int ks = 0; ks < kcnt; ks++) {
            uint32_t Fa[4][4];
            int ch_a = (ks << 1) + a_sel;
#pragma unroll
            for (int mi = 0; mi < 4; mi++) {
                int rr = a_row + mi * 16;
                ldm_x4(Fa[mi], base + ((uint32_t)rr << 7) + (((uint32_t)(ch_a ^ (rr & 7))) << 4));
            }
            int ch_b = (ks << 1) + b_ksel;
#pragma unroll
            for (int np = 0; np < 2; np++) {
                int nr = b_row4 + np * 16;
                uint32_t B4[4];
                ldm_x4(B4, base + 16384 + ((uint32_t)nr << 7)
                           + (((uint32_t)(ch_b ^ (nr & 7))) << 4));
#pragma unroll
                for (int mi = 0; mi < 4; mi++) {
                    mma_f16(acc[mi][np * 2],     Fa[mi], B4[0], B4[1]);
                    mma_f16(acc[mi][np * 2 + 1], Fa[mi], B4[2], B4[3]);
                }
            }
        }
        g_fill(A, W, K, row0, col0, s + 2, nst, sb, tid);
    }

    int er = row0 + warp_m * 64 + (lane >> 2);
    int ec = col0 + warp_n * 32 + ((lane & 3) << 1);
    if (mode != 2) {
#pragma unroll
        for (int ni = 0; ni < 4; ni++) {
            int c = ec + ni * 8;
            float b0 = __ldg(bias + c), b1 = __ldg(bias + c + 1);
#pragma unroll
            for (int mi = 0; mi < 4; mi++) {
                int r = er + mi * 16;
                float v00 = acc[mi][ni][0] + b0, v01 = acc[mi][ni][1] + b1;
                float v10 = acc[mi][ni][2] + b0, v11 = acc[mi][ni][3] + b1;
                if (relu) {
                    v00 = fmaxf(v00, 0.f); v01 = fmaxf(v01, 0.f);
                    v10 = fmaxf(v10, 0.f); v11 = fmaxf(v11, 0.f);
                }
                if (mode == 0) {
                    *(float2*)(Cf + (size_t)r * N + c)       = make_float2(v00, v01);
                    *(float2*)(Cf + (size_t)(r + 8) * N + c) = make_float2(v10, v11);
                } else {
                    *(__half2*)(Ch + (size_t)r * N + c)       = __floats2half2_rn(v00, v01);
                    *(__half2*)(Ch + (size_t)(r + 8) * N + c) = __floats2half2_rn(v10, v11);
                }
            }
        }
    } else {
        // fused per-batch (1000 rows) column max -> Cf[batch][N] via atomicMax.
        int bat0 = row0 / 1000;
        int cut = (bat0 + 1) * 1000;
        bool has2 = (row0 + 127 >= cut);
        int* outI = (int*)Cf;
#pragma unroll
        for (int ni = 0; ni < 4; ni++) {
            int c = ec + ni * 8;
            float b0 = __ldg(bias + c), b1 = __ldg(bias + c + 1);
            float s00 = 0.f, s01 = 0.f, s10 = 0.f, s11 = 0.f;
#pragma unroll
            for (int mi = 0; mi < 4; mi++) {
                int r = er + mi * 16;
                float v00 = fmaxf(acc[mi][ni][0] + b0, 0.f);
                float v01 = fmaxf(acc[mi][ni][1] + b1, 0.f);
                float v10 = fmaxf(acc[mi][ni][2] + b0, 0.f);
                float v11 = fmaxf(acc[mi][ni][3] + b1, 0.f);
                if (r < cut)     { s00 = fmaxf(s00, v00); s01 = fmaxf(s01, v01); }
                else             { s10 = fmaxf(s10, v00); s11 = fmaxf(s11, v01); }
                if (r + 8 < cut) { s00 = fmaxf(s00, v10); s01 = fmaxf(s01, v11); }
                else             { s10 = fmaxf(s10, v10); s11 = fmaxf(s11, v11); }
            }
#pragma unroll
            for (int d = 4; d <= 16; d <<= 1) {
                s00 = fmaxf(s00, __shfl_xor_sync(0xffffffffu, s00, d));
                s01 = fmaxf(s01, __shfl_xor_sync(0xffffffffu, s01, d));
                s10 = fmaxf(s10, __shfl_xor_sync(0xffffffffu, s10, d));
                s11 = fmaxf(s11, __shfl_xor_sync(0xffffffffu, s11, d));
            }
            if ((lane >> 2) == 0) {
                atomicMax(outI + bat0 * N + c,     __float_as_int(s00));
                atomicMax(outI + bat0 * N + c + 1, __float_as_int(s01));
                if (has2) {
                    atomicMax(outI + (bat0 + 1) * N + c,     __float_as_int(s10));
                    atomicMax(outI + (bat0 + 1) * N + c + 1, __float_as_int(s11));
                }
            }
        }
    }
}

// ---------------- out init ----------------
__global__ void init_out(float* __restrict__ out) {
    int t = blockIdx.x * 256 + threadIdx.x;
    if (t < BATCH * 512) out[t] = 0.f;
}

// ---------------- weight pack (fp32 -> fp16, pad K) ----------------
__global__ void pack_w(const float* __restrict__ w2, const float* __restrict__ pc1,
                       const float* __restrict__ w3, const float* __restrict__ w4,
                       const float* __restrict__ pc2, const float* __restrict__ w5,
                       const float* __restrict__ w6) {
    int t = blockIdx.x * 256 + threadIdx.x;
    if (t >= 742400) return;
    float v;
    if (t < 81920) {
        v = (t < 16384) ? w2[t] : pc1[t - 16384];
    } else if (t < 149504) {
        int i = t - 81920; int r = i / 264, c = i - r * 264;
        v = (c < 259) ? w3[r * 259 + c] : 0.f;
    } else if (t < 247808) {
        v = w4[t - 149504];
    } else if (t < 395264) {
        v = pc2[t - 247808];
    } else if (t < 545792) {
        int i = t - 395264; int r = i / 392, c = i - r * 392;
        v = (c < 387) ? w5[r * 387 + c] : 0.f;
    } else {
        v = w6[t - 545792];
    }
    g_wH[t] = __float2half_rn(v);
}

// ---------------- fused conf + concat + first linear -> fp16 (4 threads/point) ----------------
__global__ void point_mlp1(const float* __restrict__ x,
                           const float* __restrict__ confW, const float* __restrict__ confb,
                           const float* __restrict__ w1, const float* __restrict__ b1) {
    int t = blockIdx.x * 256 + threadIdx.x;
    if (t >= NROWS * 4) return;
    int p = t >> 2, g = t & 3;
    float x0 = x[p * 3], x1 = x[p * 3 + 1], x2 = x[p * 3 + 2];
    float s = confW[0] * x0 + confW[1] * x1 + confW[2] * x2 + confb[0];
    float conf = 1.f / (1.f + expf(-s));
    const float* wr = w1 + (g * 16) * 4;
    __half h[16];
#pragma unroll
    for (int r = 0; r < 16; r++) {
        float a = __ldg(b1 + g * 16 + r)
                + __ldg(wr + r * 4 + 0) * conf + __ldg(wr + r * 4 + 1) * x0
                + __ldg(wr + r * 4 + 2) * x1   + __ldg(wr + r * 4 + 3) * x2;
        h[r] = __float2half_rn(fmaxf(a, 0.f));
    }
    size_t o = (size_t)p * 64 + g * 16;
    *(uint4*)(g_actP + o)     = *(uint4*)h;
    *(uint4*)(g_actP + o + 8) = *(uint4*)(h + 8);
}

// ---------------- farthest point sampling (bitwise-matches XLA) ----------------
__global__ void fps_run(const float* __restrict__ x, const int* __restrict__ far0,
                        int* __restrict__ idxout, int npoint) {
    __shared__ float sxx[512], sxy[512], sxz[512];
    int b = blockIdx.x;
    int* out = idxout + b * npoint;
    int far = far0[b];
    const float* xb = x + (size_t)b * NPT * 3;
    int lane = threadIdx.x;

    float px[16], py[16], pz[16], dist[16];
#pragma unroll
    for (int j = 0; j < 16; j++) {
        int p = j * 32 + lane;
        if (p < NPT) {
            px[j] = xb[p * 3]; py[j] = xb[p * 3 + 1]; pz[j] = xb[p * 3 + 2];
            dist[j] = 1e10f;
            sxx[p] = px[j]; sxy[p] = py[j]; sxz[p] = pz[j];
        } else {
            px[j] = 0.f; py[j] = 0.f; pz[j] = 0.f;
            dist[j] = -1.0f;
        }
    }
    __syncwarp();

    for (int t = 0; t < npoint; t++) {
        if (lane == 0) out[t] = far;
        if (t + 1 == npoint) break;
        float cx = sxx[far], cy = sxy[far], cz = sxz[far];
        float nd[16];
#pragma unroll
        for (int j = 0; j < 16; j++) {
            float dx = __fsub_rn(px[j], cx);
            float dy = __fsub_rn(py[j], cy);
            float dz = __fsub_rn(pz[j], cz);
            float d  = __fadd_rn(__fadd_rn(__fmul_rn(dx, dx), __fmul_rn(dy, dy)),
                                 __fmul_rn(dz, dz));
            nd[j] = fminf(dist[j], d);
            dist[j] = nd[j];
        }
        float m[8];
#pragma unroll
        for (int j = 0; j < 8; j++) m[j] = fmaxf(nd[2 * j], nd[2 * j + 1]);
#pragma unroll
        for (int j = 0; j < 4; j++) m[j] = fmaxf(m[j], m[j + 4]);
        m[0] = fmaxf(m[0], m[2]); m[1] = fmaxf(m[1], m[3]);
        float best = fmaxf(m[0], m[1]);
        unsigned mb = __reduce_max_sync(0xffffffffu, __float_as_uint(best));
        unsigned c[16];
#pragma unroll
        for (int j = 0; j < 16; j++)
            c[j] = (__float_as_uint(nd[j]) == mb) ? (unsigned)(j * 32 + lane) : 0xffffffffu;
#pragma unroll
        for (int j = 0; j < 8; j++) c[j] = min(c[j], c[j + 8]);
#pragma unroll
        for (int j = 0; j < 4; j++) c[j] = min(c[j], c[j + 4]);
        c[0] = min(c[0], c[2]); c[1] = min(c[1], c[3]);
        far = (int)__reduce_min_sync(0xffffffffu, min(c[0], c[1]));
    }
}

// ---------------- gathers (fp16, 16B chunks; zero K-pad) ----------------
__global__ void gather1b(const float* __restrict__ x) {
    int t = blockIdx.x * 256 + threadIdx.x;
    if (t >= NROWS * 33) return;
    int r = t / 33, c = t - r * 33;
    int b = r / 500;
    int i = g_idx1[r];
    size_t src = (size_t)b * 500 + i;
    size_t drow = (size_t)r * 264;
    if (c < 32) {
        *(uint4*)(g_actQ + drow + c * 8) = *(const uint4*)(g_actP + src * 256 + c * 8);
    } else {
        const float* xp = x + src * 3;
        __half h[8];
#pragma unroll
        for (int j = 0; j < 8; j++) h[j] = __float2half(0.f);
#pragma unroll
        for (int j = 0; j < 3; j++) h[j] = __float2half_rn(xp[j]);
        *(uint4*)(g_actQ + drow + 256) = *(uint4*)h;
    }
}
__global__ void gather2b(const float* __restrict__ x) {
    int t = blockIdx.x * 256 + threadIdx.x;
    if (t >= 128000 * 49) return;
    int r = t / 49, c = t - r * 49;
    int b = r / 1000;
    int i = g_idx2[r];
    size_t src = (size_t)b * 500 + i;
    size_t drow = (size_t)r * 392;
    if (c < 48) {
        *(uint4*)(g_actQ + drow + c * 8) = *(const uint4*)(g_actP + src * 384 + c * 8);
    } else {
        const float* xp = x + src * 3;
        __half h[8];
#pragma unroll
        for (int j = 0; j < 8; j++) h[j] = __float2half(0.f);
#pragma unroll
        for (int j = 0; j < 3; j++) h[j] = __float2half_rn(xp[j]);
        *(uint4*)(g_actQ + drow + 384) = *(uint4*)h;
    }
}

// ---------------- launch ----------------
extern "C" void kernel_launch(void* const* d_in, const int* in_sizes, int n_in,
                              void* d_out, int out_size) {
    const float* x     = (const float*)d_in[0];
    const float* confW = (const float*)d_in[1];
    const float* confb = (const float*)d_in[2];
    const float* w1    = (const float*)d_in[3];
    const float* b1    = (const float*)d_in[4];
    const float* w2    = (const float*)d_in[5];
    const float* b2    = (const float*)d_in[6];
    const float* pc1W  = (const float*)d_in[7];
    const float* pc1b  = (const float*)d_in[8];
    const float* w3    = (const float*)d_in[9];
    const float* b3    = (const float*)d_in[10];
    const float* w4    = (const float*)d_in[11];
    const float* b4    = (const float*)d_in[12];
    const float* pc2W  = (const float*)d_in[13];
    const float* pc2b  = (const float*)d_in[14];
    const float* w5    = (const float*)d_in[15];
    const float* b5    = (const float*)d_in[16];
    const float* w6    = (const float*)d_in[17];
    const float* b6    = (const float*)d_in[18];
    const int* far1    = (const int*)d_in[20];
    const int* far2    = (const int*)d_in[21];
    float* out = (float*)d_out;

    __half *actP, *actQ, *wH;
    int *idx1, *idx2;
    cudaGetSymbolAddress((void**)&actP, g_actP);
    cudaGetSymbolAddress((void**)&actQ, g_actQ);
    cudaGetSymbolAddress((void**)&wH,   g_wH);
    cudaGetSymbolAddress((void**)&idx1, g_idx1);
    cudaGetSymbolAddress((void**)&idx2, g_idx2);

    cudaFuncSetAttribute(gemm_f16, cudaFuncAttributeMaxDynamicSharedMemorySize, GEMM_SMEM);

    // one-time host-side resources for FPS side streams
    static cudaStream_t s1 = nullptr, s2 = nullptr;
    static cudaEvent_t evA = nullptr, ev1 = nullptr, ev2 = nullptr;
    if (s1 == nullptr) {
        cudaStreamCreateWithFlags(&s1, cudaStreamNonBlocking);
        cudaStreamCreateWithFlags(&s2, cudaStreamNonBlocking);
        cudaEventCreateWithFlags(&evA, cudaEventDisableTiming);
        cudaEventCreateWithFlags(&ev1, cudaEventDisableTiming);
        cudaEventCreateWithFlags(&ev2, cudaEventDisableTiming);
    }

    init_out<<<(BATCH * 512 + 255) / 256, 256>>>(out);

    // fork: FPS1 on s1, FPS2 on s2, concurrent with main-stream GEMM chain
    cudaEventRecord(evA, 0);
    cudaStreamWaitEvent(s1, evA, 0);
    cudaStreamWaitEvent(s2, evA, 0);
    fps_run<<<BATCH, 32, 0, s1>>>(x, far1, idx1, 500);
    cudaEventRecord(ev1, s1);
    fps_run<<<BATCH, 32, 0, s2>>>(x, far2, idx2, 1000);
    cudaEventRecord(ev2, s2);

    pack_w<<<(742400 + 255) / 256, 256>>>(w2, pc1W, w3, w4, pc2W, w5, w6);
    point_mlp1<<<(NROWS * 4 + 255) / 256, 256>>>(x, confW, confb, w1, b1);

    // l2: (64000x256, K=64), relu
    gemm_f16<<<dim3(2, 500), 256, GEMM_SMEM>>>(actP, wH + OFF_W2,
        b2, nullptr, actQ, NROWS, 256, 64, 1, 1);
    // l3: (64000x256, K=256)
    gemm_f16<<<dim3(2, 500), 256, GEMM_SMEM>>>(actQ, wH + OFF_PC1,
        pc1b, nullptr, actP, NROWS, 256, 256, 0, 1);

    // join idx1 only (FPS2 keeps running under l4-l6)
    cudaStreamWaitEvent(0, ev1, 0);
    gather1b<<<(NROWS * 33 + 255) / 256, 256>>>(x);
    // l4: (64000x256, K=264), relu
    gemm_f16<<<dim3(2, 500), 256, GEMM_SMEM>>>(actQ, wH + OFF_W3,
        b3, nullptr, actP, NROWS, 256, 264, 1, 1);
    // l5: (64000x384, K=256), relu
    gemm_f16<<<dim3(3, 500), 256, GEMM_SMEM>>>(actP, wH + OFF_W4,
        b4, nullptr, actQ, NROWS, 384, 256, 1, 1);
    // l6: (64000x384, K=384)
    gemm_f16<<<dim3(3, 500), 256, GEMM_SMEM>>>(actQ, wH + OFF_PC2,
        pc2b, nullptr, actP, NROWS, 384, 384, 0, 1);

    // join idx2
    cudaStreamWaitEvent(0, ev2, 0);
    gather2b<<<(128000 * 49 + 255) / 256, 256>>>(x);
    // l7: (128000x384, K=392), relu
    gemm_f16<<<dim3(3, 1000), 256, GEMM_SMEM>>>(actQ, wH + OFF_W5,
        b5, nullptr, actP, 128000, 384, 392, 1, 1);
    // l8: (128000x512, K=384), relu, FUSED max-pool -> out
    gemm_f16<<<dim3(4, 1000), 256, GEMM_SMEM>>>(actP, wH + OFF_W6,
        b6, out, nullptr, 128000, 512, 384, 1, 2);
}